// round 3
// baseline (speedup 1.0000x reference)
#include <cuda_runtime.h>
#include <cstdint>

#define B_      2
#define I_      1024
#define J_      1024
#define C_      64
#define TJ      32
#define NT      (J_/TJ)     // 32
#define ROWS    2
#define THREADS 64
#define KPAD    17          // float4 per K row in smem (conflict-free)

typedef unsigned long long ull;

__device__ __forceinline__ float tanh_apx(float x) {
    float y; asm("tanh.approx.f32 %0, %1;" : "=f"(y) : "f"(x)); return y;
}
__device__ __forceinline__ ull pk2(float lo, float hi) {
    ull r; asm("mov.b64 %0, {%1, %2};" : "=l"(r) : "f"(lo), "f"(hi)); return r;
}
__device__ __forceinline__ void upk2(ull a, float& lo, float& hi) {
    asm("mov.b64 {%0, %1}, %2;" : "=f"(lo), "=f"(hi) : "l"(a));
}
__device__ __forceinline__ ull fma2(ull a, ull b, ull c) {
    ull d; asm("fma.rn.f32x2 %0, %1, %2, %3;" : "=l"(d) : "l"(a), "l"(b), "l"(c)); return d;
}
__device__ __forceinline__ ull add2(ull a, ull b) {
    ull d; asm("add.rn.f32x2 %0, %1, %2;" : "=l"(d) : "l"(a), "l"(b)); return d;
}
__device__ __forceinline__ void cp16(uint32_t s, const void* g) {
    asm volatile("cp.async.cg.shared.global [%0], [%1], 16;" :: "r"(s), "l"(g));
}
__device__ __forceinline__ void cp_commit() { asm volatile("cp.async.commit_group;"); }
template<int N> __device__ __forceinline__ void cp_wait() {
    asm volatile("cp.async.wait_group %0;" :: "n"(N));
}

__global__ __launch_bounds__(THREADS)
void fused_attn_mlp_kernel(const float* __restrict__ Q,
                           const float* __restrict__ K,
                           const float* __restrict__ bias,
                           const float* __restrict__ mask,
                           float* __restrict__ out,      // [B,I,C]
                           float* __restrict__ attn)     // [B,I,J]
{
    __shared__ __align__(16) float4 kbuf[2][TJ * KPAD];  // 2 x 8.7KB
    __shared__ __align__(16) float4 sq[ROWS][16];        // 0.5*Q rows
    __shared__ __align__(16) float4 sbv[16];             // 0.5*bias

    const int tid  = threadIdx.x;
    const int lane = tid & 31;
    const int w    = tid >> 5;            // warp = local row (0/1)
    const int half = lane >> 4;           // 0: ch 0-31, 1: ch 32-63
    const int lj   = lane & 15;           // j within 16-group
    const int row  = blockIdx.x * ROWS + w;
    const int b    = (blockIdx.x * ROWS) >> 10;
    const int half8 = half * 8;           // float4 offset of this half

    if (tid < C_) ((float*)sbv)[tid] = 0.5f * bias[tid];
    #pragma unroll
    for (int p = 0; p < (ROWS * C_) / THREADS; ++p) {
        int idx = tid + p * THREADS;
        int r = idx >> 6, c = idx & 63;
        ((float*)sq)[idx] = 0.5f * Q[(size_t)(blockIdx.x * ROWS + r) * C_ + c];
    }

    const uint32_t sbase0 = (uint32_t)__cvta_generic_to_shared(&kbuf[0][0]);
    const uint32_t sbase1 = (uint32_t)__cvta_generic_to_shared(&kbuf[1][0]);
    const float4* Kb = (const float4*)K + (size_t)b * J_ * 16;

    // prefetch tile 0: TJ*16 = 512 chunks / 64 thr = 8 per thread
    {
        #pragma unroll
        for (int p = 0; p < (TJ * 16) / THREADS; ++p) {
            int idx = tid + p * THREADS;
            int r = idx >> 4, c = idx & 15;
            cp16(sbase0 + (uint32_t)(r * KPAD + c) * 16, Kb + (size_t)r * 16 + c);
        }
        cp_commit();
    }
    __syncthreads();

    float ssum = 0.f;
    #pragma unroll
    for (int c = 0; c < C_; ++c) ssum += ((const float*)sbv)[c];

    ull acc2[16];
    #pragma unroll
    for (int c = 0; c < 16; ++c) acc2[c] = 0ull;   // bits of (0.f,0.f)
    float msum = 0.f;

    const float* mrow = mask + (size_t)row * J_;
    float*       arow = attn + (size_t)row * J_;

    const ulonglong2* qp = (const ulonglong2*)(&sq[w][half8]);
    const ulonglong2* bp = (const ulonglong2*)(&sbv[half8]);

    for (int t = 0; t < NT; ++t) {
        // masks for this tile (independent of smem state)
        const float m0 = mrow[t * TJ + lj];
        const float m1 = mrow[t * TJ + 16 + lj];

        if (t + 1 < NT) {
            const float4* src = Kb + (size_t)(t + 1) * TJ * 16;
            uint32_t dst = ((t + 1) & 1) ? sbase1 : sbase0;
            #pragma unroll
            for (int p = 0; p < (TJ * 16) / THREADS; ++p) {
                int idx = tid + p * THREADS;
                int r = idx >> 4, c = idx & 15;
                cp16(dst + (uint32_t)(r * KPAD + c) * 16, src + (size_t)r * 16 + c);
            }
            cp_commit();
            cp_wait<1>();
        } else {
            cp_wait<0>();
        }
        __syncthreads();

        const float4* kb = kbuf[t & 1];

        #pragma unroll
        for (int u = 0; u < TJ / 16; ++u) {
            const int jj = u * 16 + lj;
            const float m = (u == 0) ? m0 : m1;
            const ull  mh2 = pk2(0.5f * m, 0.5f * m);
            const ulonglong2* kr = (const ulonglong2*)(kb + jj * KPAD + half8);

            ull hs2 = 0ull;
            #pragma unroll
            for (int c = 0; c < 8; ++c) {
                const ulonglong2 k2 = kr[c];
                const ulonglong2 q2 = qp[c];
                const ulonglong2 b2 = bp[c];
                const ull ha = fma2(q2.x, k2.x, b2.x);
                const ull hb = fma2(q2.y, k2.y, b2.y);
                hs2 = add2(hs2, add2(ha, hb));
                float h0, h1, h2, h3;
                upk2(ha, h0, h1);
                upk2(hb, h2, h3);
                const ull ta = pk2(tanh_apx(h0), tanh_apx(h1));
                const ull tb = pk2(tanh_apx(h2), tanh_apx(h3));
                acc2[2 * c]     = fma2(ta, mh2, acc2[2 * c]);
                acc2[2 * c + 1] = fma2(tb, mh2, acc2[2 * c + 1]);
            }
            float hl, hh;
            upk2(hs2, hl, hh);
            float hs = hl + hh;                        // this half's 32-ch sum
            hs += __shfl_xor_sync(0xffffffffu, hs, 16); // full 64-ch sum
            if (half == 0) arow[t * TJ + jj] = 2.0f * (hs - ssum) * m;
            msum += m;
        }
        __syncthreads();
    }

    // reduce within each 16-lane group (lanes stay inside their channel half)
    #pragma unroll
    for (int s = 1; s < 16; s <<= 1) {
        msum += __shfl_xor_sync(0xffffffffu, msum, s);
        #pragma unroll
        for (int c = 0; c < 16; ++c)
            acc2[c] = add2(acc2[c], __shfl_xor_sync(0xffffffffu, acc2[c], s));
    }

    if (lj == 0) {  // lane 0 writes ch 0-31, lane 16 writes ch 32-63
        const float hm  = 0.5f * msum;
        const float inv = __fdividef(1.0f, msum);
        float* orow = out + (size_t)row * C_ + half * 32;
        #pragma unroll
        for (int c = 0; c < 16; ++c) {
            float a, d;
            upk2(acc2[c], a, d);
            float2 o = make_float2((a + hm) * inv, (d + hm) * inv);
            *(float2*)(orow + c * 2) = o;
        }
    }
}

extern "C" void kernel_launch(void* const* d_in, const int* in_sizes, int n_in,
                              void* d_out, int out_size) {
    const float* Q    = (const float*)d_in[0];
    const float* K    = (const float*)d_in[1];
    const float* bias = (const float*)d_in[2];
    const float* mask = (const float*)d_in[3];
    float* out  = (float*)d_out;                       // [B,I,C] first
    float* attn = (float*)d_out + (size_t)B_*I_*C_;    // [B,I,J] second

    dim3 grid(B_ * I_ / ROWS);
    dim3 block(THREADS);
    fused_attn_mlp_kernel<<<grid, block>>>(Q, K, bias, mask, out, attn);
}